// round 10
// baseline (speedup 1.0000x reference)
#include <cuda_runtime.h>
#include <cuda_bf16.h>
#include <cuda_fp16.h>
#include <cstdint>

#define NN 100000
#define NE 3200000
#define NG 256
#define NF 64
#define NBLK 98   // ceil(NN/1024)

// -------- scratch (no allocations allowed) --------
__device__ float  g_deg[NN];
__device__ float  g_dinv[NN];
__device__ float  g_p[NN];                  // x * dinv
__device__ float  g_a[NN];                  // layer-1 aggregate
__device__ int    g_icnt[NN];               // in-degree histogram
__device__ int    g_off[NN];                // CSR offsets (exclusive scan)
__device__ int    g_rank[NE];               // rank of edge within its dst row
__device__ int    g_bsum[NBLK];             // per-block totals
__device__ int    g_boff[NBLK];             // scanned block offsets
__device__ unsigned long long g_epack[NE];  // dst-sorted edges: (w<<32)|r
__device__ __half g_sh[NN * 64];            // s1 = (h1 @ W2) * dinv, fp16 [N,64]
__device__ float  g_gsum[NG * NF];
__device__ float  g_gcnt[NG];

__device__ __forceinline__ float gelu_t(float x) {
    const float c = 0.7978845608028654f;
    float t = tanhf(c * (x + 0.044715f * x * x * x));
    return 0.5f * x * (1.0f + t);
}

__device__ __forceinline__ void red_add_v4(float* addr, float a, float b, float c, float d) {
    asm volatile("red.global.add.v4.f32 [%0], {%1,%2,%3,%4};"
                 :: "l"(addr), "f"(a), "f"(b), "f"(c), "f"(d)
                 : "memory");
}

// K0: init deg=1 (self loop), zero histogram + pool buffers
__global__ void k0_init() {
    int i = blockIdx.x * blockDim.x + threadIdx.x;
    if (i < NN) { g_deg[i] = 1.0f; g_icnt[i] = 0; }
    if (i < NG * NF) g_gsum[i] = 0.0f;
    if (i < NG) g_gcnt[i] = 0.0f;
}

// K1: fused histogram + weighted degree; atomic return value = rank in dst row
__global__ void __launch_bounds__(256) k1_histdeg(const int* __restrict__ ei,
                                                  const float* __restrict__ ew) {
    int e = blockIdx.x * blockDim.x + threadIdx.x;
    if (e >= NE) return;
    int c = __ldg(&ei[NE + e]);
    g_rank[e] = atomicAdd(&g_icnt[c], 1);
    atomicAdd(&g_deg[c], __ldg(&ew[e]));
}

// K2: dinv = rsqrt(deg); p = x*dinv
__global__ void k2_dinv(const float* __restrict__ x) {
    int i = blockIdx.x * blockDim.x + threadIdx.x;
    if (i >= NN) return;
    float d = rsqrtf(g_deg[i]);
    g_dinv[i] = d;
    g_p[i] = x[i] * d;
}

// --- hierarchical exclusive scan of g_icnt ---
__global__ void __launch_bounds__(1024) k_scanA() {
    __shared__ int wsum[32];
    int t = threadIdx.x, b = blockIdx.x;
    int i = b * 1024 + t;
    int v = (i < NN) ? g_icnt[i] : 0;
    int lane = t & 31, wid = t >> 5;
    int s = v;
    #pragma unroll
    for (int d = 1; d < 32; d <<= 1) {
        int u = __shfl_up_sync(0xffffffffu, s, d);
        if (lane >= d) s += u;
    }
    if (lane == 31) wsum[wid] = s;
    __syncthreads();
    if (wid == 0) {
        int ws = wsum[lane];
        #pragma unroll
        for (int d = 1; d < 32; d <<= 1) {
            int u = __shfl_up_sync(0xffffffffu, ws, d);
            if (lane >= d) ws += u;
        }
        wsum[lane] = ws;
    }
    __syncthreads();
    int excl = s - v + (wid > 0 ? wsum[wid - 1] : 0);
    if (i < NN) g_off[i] = excl;
    if (t == 1023) g_bsum[b] = wsum[31];
}

__global__ void __launch_bounds__(128) k_scanB() {
    __shared__ int wsum[4];
    int t = threadIdx.x;
    int v = (t < NBLK) ? g_bsum[t] : 0;
    int lane = t & 31, wid = t >> 5;
    int s = v;
    #pragma unroll
    for (int d = 1; d < 32; d <<= 1) {
        int u = __shfl_up_sync(0xffffffffu, s, d);
        if (lane >= d) s += u;
    }
    if (lane == 31) wsum[wid] = s;
    __syncthreads();
    if (wid == 0 && lane < 4) {
        int ws = wsum[lane];
        #pragma unroll
        for (int d = 1; d < 4; d <<= 1) {
            int u = __shfl_up_sync(0x0000000fu, ws, d);
            if (lane >= d) ws += u;
        }
        wsum[lane] = ws;
    }
    __syncthreads();
    int excl = s - v + (wid > 0 ? wsum[wid - 1] : 0);
    if (t < NBLK) g_boff[t] = excl;
}

__global__ void __launch_bounds__(1024) k_scanC() {
    int i = blockIdx.x * 1024 + threadIdx.x;
    if (i >= NN) return;
    g_off[i] += g_boff[blockIdx.x];
}

// KP: placement scatter (no atomics) — build dst-sorted packed edge list
__global__ void __launch_bounds__(256) k_place(const int* __restrict__ ei,
                                               const float* __restrict__ ew) {
    int e = blockIdx.x * blockDim.x + threadIdx.x;
    if (e >= NE) return;
    int r = __ldg(&ei[e]);
    int c = __ldg(&ei[NE + e]);
    float w = __ldg(&ew[e]);
    int pos = g_off[c] + g_rank[e];
    g_epack[pos] = ((unsigned long long)__float_as_uint(w) << 32) | (unsigned int)r;
}

// K3b: layer-1 aggregation, gather form: a[v] = p[v] + sum p[r]*w
__global__ void __launch_bounds__(256) k3b_gatherA() {
    int v = blockIdx.x * blockDim.x + threadIdx.x;
    if (v >= NN) return;
    float acc = g_p[v];
    int i = g_off[v];
    int end = i + g_icnt[v];
    #pragma unroll 4
    for (; i < end; i++) {
        unsigned long long pk = __ldg(&g_epack[i]);
        int   r = (int)(pk & 0xffffffffu);
        float w = __uint_as_float((unsigned int)(pk >> 32));
        acc = fmaf(w, g_p[r], acc);
    }
    g_a[v] = acc;
}

// K4: h1 = gelu(a*dinv*W1 + b1); s1 = (h1 @ W2)*dinv -> fp16
__global__ void __launch_bounds__(256) k4_layer1(const float* __restrict__ W1,
                                                 const float* __restrict__ b1,
                                                 const float* __restrict__ W2) {
    __shared__ float W2s[NF * NF];
    __shared__ float hbuf[4][NF];
    int f  = threadIdx.x;
    int ny = threadIdx.y;
    int tid = ny * 64 + f;
    #pragma unroll
    for (int i = 0; i < 16; i++) W2s[tid + i * 256] = W2[tid + i * 256];

    int v = blockIdx.x * 4 + ny;   // NN % 4 == 0
    float ad = g_a[v] * g_dinv[v];
    float h = gelu_t(ad * __ldg(&W1[f]) + __ldg(&b1[f]));
    hbuf[ny][f] = h;
    __syncthreads();

    float t = 0.0f;
    #pragma unroll 8
    for (int k = 0; k < NF; k++) t = fmaf(hbuf[ny][k], W2s[k * NF + f], t);
    g_sh[v * NF + f] = __float2half_rn(t * g_dinv[v]);
}

// K5b: layer-2 gather (fp16 rows, fp32 accum) fused with gelu + pool.
// 16 lanes per node; coalesced cooperative edge loads broadcast via shfl.
__global__ void __launch_bounds__(256) k5b_gatherB(const int* __restrict__ batch,
                                                   const float* __restrict__ b2) {
    int t = blockIdx.x * blockDim.x + threadIdx.x;   // < NN*16
    int v = t >> 4;
    int j = t & 15;
    if (v >= NN) return;
    int lane = threadIdx.x & 31;
    int gbase = lane & 16;                    // 16-lane group base within warp
    unsigned hm = 0xFFFFu << gbase;           // own half-warp mask

    // self-loop term (read own fp16 slice)
    float4 acc;
    {
        uint2 sv = *(const uint2*)(g_sh + v * 64 + j * 4);
        float2 lo = __half22float2(*(__half2*)&sv.x);
        float2 hi = __half22float2(*(__half2*)&sv.y);
        acc.x = lo.x; acc.y = lo.y; acc.z = hi.x; acc.w = hi.y;
    }

    int i = g_off[v];
    int end = i + g_icnt[v];
    for (; i < end; i += 16) {
        int idx = i + j;
        unsigned long long pk = (idx < end) ? __ldg(&g_epack[idx]) : 0ULL; // w=0 pad
        #pragma unroll
        for (int k = 0; k < 16; k++) {
            unsigned long long pkk = __shfl_sync(hm, pk, gbase + k);
            int   r = (int)(pkk & 0xffffffffu);
            float w = __uint_as_float((unsigned int)(pkk >> 32));
            uint2 sv = __ldg((const uint2*)(g_sh + r * 64 + j * 4));
            float2 lo = __half22float2(*(__half2*)&sv.x);
            float2 hi = __half22float2(*(__half2*)&sv.y);
            acc.x = fmaf(w, lo.x, acc.x);
            acc.y = fmaf(w, lo.y, acc.y);
            acc.z = fmaf(w, hi.x, acc.z);
            acc.w = fmaf(w, hi.y, acc.w);
        }
    }

    float di = g_dinv[v];
    const float4 bj = __ldg(&((const float4*)b2)[j]);
    float h0 = gelu_t(fmaf(acc.x, di, bj.x));
    float h1 = gelu_t(fmaf(acc.y, di, bj.y));
    float h2 = gelu_t(fmaf(acc.z, di, bj.z));
    float h3 = gelu_t(fmaf(acc.w, di, bj.w));

    int g = __ldg(&batch[v]);
    red_add_v4(&g_gsum[g * NF + j * 4], h0, h1, h2, h3);
    if (j == 0) atomicAdd(&g_gcnt[g], 1.0f);
}

// K7: final MLP over 256 graphs
__global__ void __launch_bounds__(256) k7_mlp(const float* __restrict__ fc1W,
                                              const float* __restrict__ fc1b,
                                              const float* __restrict__ fc2W,
                                              const float* __restrict__ fc2b,
                                              float* __restrict__ out) {
    __shared__ float W1s[64 * 32];
    __shared__ float b1s[32];
    __shared__ float W2s[32];
    int g = threadIdx.x;
    #pragma unroll
    for (int i = 0; i < 8; i++) W1s[g + i * 256] = fc1W[g + i * 256];
    if (g < 32) { b1s[g] = fc1b[g]; W2s[g] = fc2W[g]; }
    __syncthreads();

    float cnt = g_gcnt[g];
    float inv = 1.0f / fmaxf(cnt, 1.0f);
    float m[64];
    #pragma unroll
    for (int k = 0; k < 64; k++) m[k] = g_gsum[g * 64 + k] * inv;

    float o = 0.0f;
    #pragma unroll 4
    for (int j = 0; j < 32; j++) {
        float z = b1s[j];
        #pragma unroll 8
        for (int k = 0; k < 64; k++) z = fmaf(m[k], W1s[k * 32 + j], z);
        o = fmaf(gelu_t(z), W2s[j], o);
    }
    out[g] = o + fc2b[0];
}

extern "C" void kernel_launch(void* const* d_in, const int* in_sizes, int n_in,
                              void* d_out, int out_size) {
    const float* x     = (const float*)d_in[0];
    const int*   ei    = (const int*)d_in[1];     // int32 (JAX x64 disabled)
    const float* ew    = (const float*)d_in[2];
    const int*   batch = (const int*)d_in[3];
    const float* W1    = (const float*)d_in[4];
    const float* b1    = (const float*)d_in[5];
    const float* W2    = (const float*)d_in[6];
    const float* b2    = (const float*)d_in[7];
    const float* fc1W  = (const float*)d_in[8];
    const float* fc1b  = (const float*)d_in[9];
    const float* fc2W  = (const float*)d_in[10];
    const float* fc2b  = (const float*)d_in[11];
    float* out = (float*)d_out;

    k0_init<<<(NG * NF + 255) / 256 > (NN + 255) / 256 ? (NG * NF + 255) / 256
                                                       : (NN + 255) / 256, 256>>>();
    k1_histdeg<<<(NE + 255) / 256, 256>>>(ei, ew);
    k2_dinv<<<(NN + 255) / 256, 256>>>(x);
    k_scanA<<<NBLK, 1024>>>();
    k_scanB<<<1, 128>>>();
    k_scanC<<<NBLK, 1024>>>();
    k_place<<<(NE + 255) / 256, 256>>>(ei, ew);
    k3b_gatherA<<<(NN + 255) / 256, 256>>>();
    k4_layer1<<<NN / 4, dim3(64, 4)>>>(W1, b1, W2);
    k5b_gatherB<<<(NN * 16 + 255) / 256, 256>>>(batch, b2);
    k7_mlp<<<1, 256>>>(fc1W, fc1b, fc2W, fc2b, out);
}

// round 12
// speedup vs baseline: 1.3983x; 1.3983x over previous
#include <cuda_runtime.h>
#include <cuda_bf16.h>
#include <cstdint>

#define NN 100000
#define NE 3200000
#define NG 256
#define NF 64
#define NBLK 98   // ceil(NN/1024)

// -------- scratch (no allocations allowed) --------
__device__ float  g_deg[NN];
__device__ float  g_dinv[NN];
__device__ float  g_p[NN];                  // x * dinv
__device__ float  g_a[NN];                  // layer-1 aggregate
__device__ int    g_icnt[NN];               // in-degree histogram
__device__ int    g_off[NN];                // CSR offsets (exclusive scan)
__device__ int    g_rank[NE];               // rank of edge within its dst row
__device__ int    g_bsum[NBLK];             // per-block totals
__device__ int    g_boff[NBLK];             // scanned block offsets
__device__ unsigned long long g_epack[NE];  // dst-sorted edges: (w<<32)|r
__device__ float4 g_s[NN * 16];             // s1 = (h1 @ W2) * dinv  [N,64] fp32
__device__ float  g_gsum[NG * NF];
__device__ float  g_gcnt[NG];

__device__ __forceinline__ float gelu_t(float x) {
    const float c = 0.7978845608028654f;
    float t = tanhf(c * (x + 0.044715f * x * x * x));
    return 0.5f * x * (1.0f + t);
}

__device__ __forceinline__ void red_add_v4(float* addr, float a, float b, float c, float d) {
    asm volatile("red.global.add.v4.f32 [%0], {%1,%2,%3,%4};"
                 :: "l"(addr), "f"(a), "f"(b), "f"(c), "f"(d)
                 : "memory");
}

// K0: init deg=1 (self loop), zero histogram + pool buffers
__global__ void k0_init() {
    int i = blockIdx.x * blockDim.x + threadIdx.x;
    if (i < NN) { g_deg[i] = 1.0f; g_icnt[i] = 0; }
    if (i < NG * NF) g_gsum[i] = 0.0f;
    if (i < NG) g_gcnt[i] = 0.0f;
}

// K1: fused histogram + weighted degree; atomic return value = rank in dst row
__global__ void __launch_bounds__(256) k1_histdeg(const int* __restrict__ ei,
                                                  const float* __restrict__ ew) {
    int e = blockIdx.x * blockDim.x + threadIdx.x;
    if (e >= NE) return;
    int c = __ldg(&ei[NE + e]);
    g_rank[e] = atomicAdd(&g_icnt[c], 1);
    atomicAdd(&g_deg[c], __ldg(&ew[e]));
}

// K2: dinv = rsqrt(deg); p = x*dinv
__global__ void k2_dinv(const float* __restrict__ x) {
    int i = blockIdx.x * blockDim.x + threadIdx.x;
    if (i >= NN) return;
    float d = rsqrtf(g_deg[i]);
    g_dinv[i] = d;
    g_p[i] = x[i] * d;
}

// --- hierarchical exclusive scan of g_icnt ---
__global__ void __launch_bounds__(1024) k_scanA() {
    __shared__ int wsum[32];
    int t = threadIdx.x, b = blockIdx.x;
    int i = b * 1024 + t;
    int v = (i < NN) ? g_icnt[i] : 0;
    int lane = t & 31, wid = t >> 5;
    int s = v;
    #pragma unroll
    for (int d = 1; d < 32; d <<= 1) {
        int u = __shfl_up_sync(0xffffffffu, s, d);
        if (lane >= d) s += u;
    }
    if (lane == 31) wsum[wid] = s;
    __syncthreads();
    if (wid == 0) {
        int ws = wsum[lane];
        #pragma unroll
        for (int d = 1; d < 32; d <<= 1) {
            int u = __shfl_up_sync(0xffffffffu, ws, d);
            if (lane >= d) ws += u;
        }
        wsum[lane] = ws;
    }
    __syncthreads();
    int excl = s - v + (wid > 0 ? wsum[wid - 1] : 0);
    if (i < NN) g_off[i] = excl;
    if (t == 1023) g_bsum[b] = wsum[31];
}

__global__ void __launch_bounds__(128) k_scanB() {
    __shared__ int wsum[4];
    int t = threadIdx.x;
    int v = (t < NBLK) ? g_bsum[t] : 0;
    int lane = t & 31, wid = t >> 5;
    int s = v;
    #pragma unroll
    for (int d = 1; d < 32; d <<= 1) {
        int u = __shfl_up_sync(0xffffffffu, s, d);
        if (lane >= d) s += u;
    }
    if (lane == 31) wsum[wid] = s;
    __syncthreads();
    if (wid == 0 && lane < 4) {
        int ws = wsum[lane];
        #pragma unroll
        for (int d = 1; d < 4; d <<= 1) {
            int u = __shfl_up_sync(0x0000000fu, ws, d);
            if (lane >= d) ws += u;
        }
        wsum[lane] = ws;
    }
    __syncthreads();
    int excl = s - v + (wid > 0 ? wsum[wid - 1] : 0);
    if (t < NBLK) g_boff[t] = excl;
}

__global__ void __launch_bounds__(1024) k_scanC() {
    int i = blockIdx.x * 1024 + threadIdx.x;
    if (i >= NN) return;
    g_off[i] += g_boff[blockIdx.x];
}

// KP: placement scatter (no atomics) — build dst-sorted packed edge list
__global__ void __launch_bounds__(256) k_place(const int* __restrict__ ei,
                                               const float* __restrict__ ew) {
    int e = blockIdx.x * blockDim.x + threadIdx.x;
    if (e >= NE) return;
    int r = __ldg(&ei[e]);
    int c = __ldg(&ei[NE + e]);
    float w = __ldg(&ew[e]);
    int pos = g_off[c] + g_rank[e];
    g_epack[pos] = ((unsigned long long)__float_as_uint(w) << 32) | (unsigned int)r;
}

// K3b: layer-1 aggregation, gather form: a[v] = p[v] + sum p[r]*w
__global__ void __launch_bounds__(256) k3b_gatherA() {
    int v = blockIdx.x * blockDim.x + threadIdx.x;
    if (v >= NN) return;
    float acc = g_p[v];
    int i = g_off[v];
    int end = i + g_icnt[v];
    #pragma unroll 4
    for (; i < end; i++) {
        unsigned long long pk = __ldg(&g_epack[i]);
        int   r = (int)(pk & 0xffffffffu);
        float w = __uint_as_float((unsigned int)(pk >> 32));
        acc = fmaf(w, g_p[r], acc);
    }
    g_a[v] = acc;
}

// K4: h1 = gelu(a*dinv*W1 + b1); s1 = (h1 @ W2)*dinv  (fp32)
__global__ void __launch_bounds__(256) k4_layer1(const float* __restrict__ W1,
                                                 const float* __restrict__ b1,
                                                 const float* __restrict__ W2) {
    __shared__ float W2s[NF * NF];
    __shared__ float hbuf[4][NF];
    int f  = threadIdx.x;
    int ny = threadIdx.y;
    int tid = ny * 64 + f;
    #pragma unroll
    for (int i = 0; i < 16; i++) W2s[tid + i * 256] = W2[tid + i * 256];

    int v = blockIdx.x * 4 + ny;   // NN % 4 == 0
    float ad = g_a[v] * g_dinv[v];
    float h = gelu_t(ad * __ldg(&W1[f]) + __ldg(&b1[f]));
    hbuf[ny][f] = h;
    __syncthreads();

    float t = 0.0f;
    #pragma unroll 8
    for (int k = 0; k < NF; k++) t = fmaf(hbuf[ny][k], W2s[k * NF + f], t);
    ((float*)g_s)[v * NF + f] = t * g_dinv[v];
}

// K5b: layer-2 gather (fp32 rows) fused with gelu + pool. 16 lanes/node.
// Cooperative coalesced edge loads broadcast via shfl; next chunk prefetched
// so the LDG overlaps the FMA chain of the current chunk.
__global__ void __launch_bounds__(256) k5b_gatherB(const int* __restrict__ batch,
                                                   const float* __restrict__ b2) {
    int t = blockIdx.x * blockDim.x + threadIdx.x;   // < NN*16
    int v = t >> 4;
    int j = t & 15;
    if (v >= NN) return;
    int lane = threadIdx.x & 31;
    int gbase = lane & 16;                    // 16-lane group base within warp
    unsigned hm = 0xFFFFu << gbase;           // own half-warp mask

    float4 acc = g_s[v * 16 + j];             // self-loop term
    int i = g_off[v];
    int end = i + g_icnt[v];

    // prefetch first chunk
    unsigned long long pk = 0ULL;
    if (i + j < end) pk = __ldg(&g_epack[i + j]);

    for (; i < end; i += 16) {
        unsigned long long cur = pk;
        int nx = i + 16 + j;
        pk = (nx < end) ? __ldg(&g_epack[nx]) : 0ULL;   // overlap with FMA chain
        #pragma unroll
        for (int k = 0; k < 16; k++) {
            unsigned long long pkk = __shfl_sync(hm, cur, gbase + k);
            int   r = (int)(pkk & 0xffffffffu);
            float w = __uint_as_float((unsigned int)(pkk >> 32));
            float4 sv = g_s[r * 16 + j];
            acc.x = fmaf(w, sv.x, acc.x);
            acc.y = fmaf(w, sv.y, acc.y);
            acc.z = fmaf(w, sv.z, acc.z);
            acc.w = fmaf(w, sv.w, acc.w);
        }
    }

    float di = g_dinv[v];
    const float4 bj = __ldg(&((const float4*)b2)[j]);
    float h0 = gelu_t(fmaf(acc.x, di, bj.x));
    float h1 = gelu_t(fmaf(acc.y, di, bj.y));
    float h2 = gelu_t(fmaf(acc.z, di, bj.z));
    float h3 = gelu_t(fmaf(acc.w, di, bj.w));

    int g = __ldg(&batch[v]);
    red_add_v4(&g_gsum[g * NF + j * 4], h0, h1, h2, h3);
    if (j == 0) atomicAdd(&g_gcnt[g], 1.0f);
}

// K7: final MLP over 256 graphs
__global__ void __launch_bounds__(256) k7_mlp(const float* __restrict__ fc1W,
                                              const float* __restrict__ fc1b,
                                              const float* __restrict__ fc2W,
                                              const float* __restrict__ fc2b,
                                              float* __restrict__ out) {
    __shared__ float W1s[64 * 32];
    __shared__ float b1s[32];
    __shared__ float W2s[32];
    int g = threadIdx.x;
    #pragma unroll
    for (int i = 0; i < 8; i++) W1s[g + i * 256] = fc1W[g + i * 256];
    if (g < 32) { b1s[g] = fc1b[g]; W2s[g] = fc2W[g]; }
    __syncthreads();

    float cnt = g_gcnt[g];
    float inv = 1.0f / fmaxf(cnt, 1.0f);
    float m[64];
    #pragma unroll
    for (int k = 0; k < 64; k++) m[k] = g_gsum[g * 64 + k] * inv;

    float o = 0.0f;
    #pragma unroll 4
    for (int j = 0; j < 32; j++) {
        float z = b1s[j];
        #pragma unroll 8
        for (int k = 0; k < 64; k++) z = fmaf(m[k], W1s[k * 32 + j], z);
        o = fmaf(gelu_t(z), W2s[j], o);
    }
    out[g] = o + fc2b[0];
}

extern "C" void kernel_launch(void* const* d_in, const int* in_sizes, int n_in,
                              void* d_out, int out_size) {
    const float* x     = (const float*)d_in[0];
    const int*   ei    = (const int*)d_in[1];     // int32 (JAX x64 disabled)
    const float* ew    = (const float*)d_in[2];
    const int*   batch = (const int*)d_in[3];
    const float* W1    = (const float*)d_in[4];
    const float* b1    = (const float*)d_in[5];
    const float* W2    = (const float*)d_in[6];
    const float* b2    = (const float*)d_in[7];
    const float* fc1W  = (const float*)d_in[8];
    const float* fc1b  = (const float*)d_in[9];
    const float* fc2W  = (const float*)d_in[10];
    const float* fc2b  = (const float*)d_in[11];
    float* out = (float*)d_out;

    k0_init<<<(NG * NF + 255) / 256 > (NN + 255) / 256 ? (NG * NF + 255) / 256
                                                       : (NN + 255) / 256, 256>>>();
    k1_histdeg<<<(NE + 255) / 256, 256>>>(ei, ew);
    k2_dinv<<<(NN + 255) / 256, 256>>>(x);
    k_scanA<<<NBLK, 1024>>>();
    k_scanB<<<1, 128>>>();
    k_scanC<<<NBLK, 1024>>>();
    k_place<<<(NE + 255) / 256, 256>>>(ei, ew);
    k3b_gatherA<<<(NN + 255) / 256, 256>>>();
    k4_layer1<<<NN / 4, dim3(64, 4)>>>(W1, b1, W2);
    k5b_gatherB<<<(NN * 16 + 255) / 256, 256>>>(batch, b2);
    k7_mlp<<<1, 256>>>(fc1W, fc1b, fc2W, fc2b, out);
}

// round 13
// speedup vs baseline: 1.4741x; 1.0542x over previous
#include <cuda_runtime.h>
#include <cuda_bf16.h>
#include <cstdint>

#define NN 100000
#define NE 3200000
#define NG 256
#define NF 64
#define NBLK 98   // ceil(NN/1024)

// -------- scratch (no allocations allowed) --------
__device__ float  g_dinv[NN];
__device__ float  g_p[NN];                  // x * dinv
__device__ float  g_a[NN];                  // layer-1 aggregate
__device__ int    g_icnt[NN];               // in-degree histogram
__device__ int    g_off[NN];                // CSR offsets (exclusive scan)
__device__ int    g_rank[NE];               // rank of edge within its dst row
__device__ int    g_bflag[NBLK];            // scan lookback flags (agg+1, 0=not ready)
__device__ unsigned long long g_epack[NE];  // dst-sorted edges: (w<<32)|r
__device__ float4 g_s[NN * 16];             // s1 = (h1 @ W2) * dinv  [N,64] fp32
__device__ float  g_gsum[NG * NF];
__device__ float  g_gcnt[NG];

__device__ __forceinline__ float gelu_t(float x) {
    const float c = 0.7978845608028654f;
    float t = tanhf(c * (x + 0.044715f * x * x * x));
    return 0.5f * x * (1.0f + t);
}

__device__ __forceinline__ void red_add_v4(float* addr, float a, float b, float c, float d) {
    asm volatile("red.global.add.v4.f32 [%0], {%1,%2,%3,%4};"
                 :: "l"(addr), "f"(a), "f"(b), "f"(c), "f"(d)
                 : "memory");
}

// packed dual-FMA: d = a*b + c elementwise on f32x2 (bit-identical to 2x fmaf)
__device__ __forceinline__ unsigned long long fma2(unsigned long long a,
                                                   unsigned long long b,
                                                   unsigned long long c) {
    unsigned long long d;
    asm("fma.rn.f32x2 %0, %1, %2, %3;" : "=l"(d) : "l"(a), "l"(b), "l"(c));
    return d;
}

// K0: zero histogram + scan flags (every graph replay)
__global__ void k0_init() {
    int i = blockIdx.x * blockDim.x + threadIdx.x;
    if (i < NN) g_icnt[i] = 0;
    if (i < NBLK) g_bflag[i] = 0;
}

// K1: histogram only (vectorized, 4 edges/thread); atomic return = rank in dst row
__global__ void __launch_bounds__(256) k1_hist(const int* __restrict__ ei) {
    int e4 = (blockIdx.x * blockDim.x + threadIdx.x) * 4;
    if (e4 >= NE) return;
    int4 cc = __ldg((const int4*)&ei[NE + e4]);
    int4 rk;
    rk.x = atomicAdd(&g_icnt[cc.x], 1);
    rk.y = atomicAdd(&g_icnt[cc.y], 1);
    rk.z = atomicAdd(&g_icnt[cc.z], 1);
    rk.w = atomicAdd(&g_icnt[cc.w], 1);
    *(int4*)&g_rank[e4] = rk;
}

// K_SCAN: single-kernel exclusive scan of g_icnt via decoupled lookback.
// 98 blocks x 1024 threads — all co-resident on 148 SMs, so spinning is safe.
__global__ void __launch_bounds__(1024) k_scan() {
    __shared__ int wsum[32];
    __shared__ int s_prefix;
    int t = threadIdx.x, b = blockIdx.x;
    int i = b * 1024 + t;
    int v = (i < NN) ? g_icnt[i] : 0;
    int lane = t & 31, wid = t >> 5;
    int s = v;
    #pragma unroll
    for (int d = 1; d < 32; d <<= 1) {
        int u = __shfl_up_sync(0xffffffffu, s, d);
        if (lane >= d) s += u;
    }
    if (lane == 31) wsum[wid] = s;
    __syncthreads();
    if (wid == 0) {
        int ws = wsum[lane];
        #pragma unroll
        for (int d = 1; d < 32; d <<= 1) {
            int u = __shfl_up_sync(0xffffffffu, ws, d);
            if (lane >= d) ws += u;
        }
        wsum[lane] = ws;
    }
    __syncthreads();
    int excl = s - v + (wid > 0 ? wsum[wid - 1] : 0);

    // publish own aggregate (value+1; 0 means not ready), then look back
    if (t == 0) atomicExch(&g_bflag[b], wsum[31] + 1);
    if (t < 32) {
        int acc = 0;
        for (int idx = t; idx < b; idx += 32) {
            int f;
            do { f = ((volatile int*)g_bflag)[idx]; } while (f == 0);
            acc += f - 1;
        }
        #pragma unroll
        for (int d = 16; d >= 1; d >>= 1)
            acc += __shfl_xor_sync(0xffffffffu, acc, d);
        if (t == 0) s_prefix = acc;
    }
    __syncthreads();
    if (i < NN) g_off[i] = excl + s_prefix;
}

// KP: placement scatter (no atomics), 4 edges/thread
__global__ void __launch_bounds__(256) k_place(const int* __restrict__ ei,
                                               const float* __restrict__ ew) {
    int e4 = (blockIdx.x * blockDim.x + threadIdx.x) * 4;
    if (e4 >= NE) return;
    int4   rr = __ldg((const int4*)&ei[e4]);
    int4   cc = __ldg((const int4*)&ei[NE + e4]);
    float4 ww = __ldg((const float4*)&ew[e4]);
    int4   rk = *(const int4*)&g_rank[e4];
    g_epack[g_off[cc.x] + rk.x] = ((unsigned long long)__float_as_uint(ww.x) << 32) | (unsigned int)rr.x;
    g_epack[g_off[cc.y] + rk.y] = ((unsigned long long)__float_as_uint(ww.y) << 32) | (unsigned int)rr.y;
    g_epack[g_off[cc.z] + rk.z] = ((unsigned long long)__float_as_uint(ww.z) << 32) | (unsigned int)rr.z;
    g_epack[g_off[cc.w] + rk.w] = ((unsigned long long)__float_as_uint(ww.w) << 32) | (unsigned int)rr.w;
}

// KA: per-node weighted degree from CSR row (+self loop), dinv, p = x*dinv
__global__ void __launch_bounds__(256) kA_degnorm(const float* __restrict__ x) {
    int v = blockIdx.x * blockDim.x + threadIdx.x;
    if (v >= NN) return;
    float deg = 1.0f;
    int i = g_off[v];
    int end = i + g_icnt[v];
    #pragma unroll 4
    for (; i < end; i++) {
        unsigned long long pk = __ldg(&g_epack[i]);
        deg += __uint_as_float((unsigned int)(pk >> 32));
    }
    float d = rsqrtf(deg);
    g_dinv[v] = d;
    g_p[v] = x[v] * d;
}

// K3b: layer-1 aggregation, gather form: a[v] = p[v] + sum p[r]*w
__global__ void __launch_bounds__(256) k3b_gatherA() {
    int v = blockIdx.x * blockDim.x + threadIdx.x;
    if (v >= NN) return;
    float acc = g_p[v];
    int i = g_off[v];
    int end = i + g_icnt[v];
    #pragma unroll 4
    for (; i < end; i++) {
        unsigned long long pk = __ldg(&g_epack[i]);
        int   r = (int)(pk & 0xffffffffu);
        float w = __uint_as_float((unsigned int)(pk >> 32));
        acc = fmaf(w, g_p[r], acc);
    }
    g_a[v] = acc;
}

// K4: h1 = gelu(a*dinv*W1 + b1); s1 = (h1 @ W2)*dinv  (fp32)
// Also zeroes the pool buffers (consumed first by k5b, which runs after).
__global__ void __launch_bounds__(256) k4_layer1(const float* __restrict__ W1,
                                                 const float* __restrict__ b1,
                                                 const float* __restrict__ W2) {
    __shared__ float W2s[NF * NF];
    __shared__ float hbuf[4][NF];
    int f  = threadIdx.x;
    int ny = threadIdx.y;
    int tid = ny * 64 + f;
    int gid = blockIdx.x * 256 + tid;
    if (gid < NG * NF) g_gsum[gid] = 0.0f;
    if (gid < NG) g_gcnt[gid] = 0.0f;
    #pragma unroll
    for (int i = 0; i < 16; i++) W2s[tid + i * 256] = W2[tid + i * 256];

    int v = blockIdx.x * 4 + ny;   // NN % 4 == 0
    float ad = g_a[v] * g_dinv[v];
    float h = gelu_t(ad * __ldg(&W1[f]) + __ldg(&b1[f]));
    hbuf[ny][f] = h;
    __syncthreads();

    float t = 0.0f;
    #pragma unroll 8
    for (int k = 0; k < NF; k++) t = fmaf(hbuf[ny][k], W2s[k * NF + f], t);
    ((float*)g_s)[v * NF + f] = t * g_dinv[v];
}

// K5b: layer-2 gather (fp32 rows, packed f32x2 FMA) fused with gelu + pool.
// 16 lanes/node; cooperative coalesced edge loads broadcast via shfl;
// next chunk prefetched to overlap the FMA chain.
__global__ void __launch_bounds__(256) k5b_gatherB(const int* __restrict__ batch,
                                                   const float* __restrict__ b2) {
    int t = blockIdx.x * blockDim.x + threadIdx.x;   // < NN*16
    int v = t >> 4;
    int j = t & 15;
    if (v >= NN) return;
    int lane = threadIdx.x & 31;
    int gbase = lane & 16;                    // 16-lane group base within warp
    unsigned hm = 0xFFFFu << gbase;           // own half-warp mask

    ulonglong2 acc = *(const ulonglong2*)&g_s[v * 16 + j];   // self-loop term
    int i = g_off[v];
    int end = i + g_icnt[v];

    unsigned long long pk = 0ULL;
    if (i + j < end) pk = __ldg(&g_epack[i + j]);

    for (; i < end; i += 16) {
        unsigned long long cur = pk;
        int nx = i + 16 + j;
        pk = (nx < end) ? __ldg(&g_epack[nx]) : 0ULL;   // overlap with FMA chain
        #pragma unroll
        for (int k = 0; k < 16; k++) {
            unsigned long long pkk = __shfl_sync(hm, cur, gbase + k);
            int          r  = (int)(pkk & 0xffffffffu);
            unsigned int wu = (unsigned int)(pkk >> 32);
            unsigned long long ww;
            asm("mov.b64 %0, {%1, %1};" : "=l"(ww) : "r"(wu));
            ulonglong2 sv = *(const ulonglong2*)&g_s[r * 16 + j];
            acc.x = fma2(sv.x, ww, acc.x);     // w=0 pad contributes exactly 0
            acc.y = fma2(sv.y, ww, acc.y);
        }
    }

    float a0 = __uint_as_float((unsigned int)acc.x);
    float a1 = __uint_as_float((unsigned int)(acc.x >> 32));
    float a2 = __uint_as_float((unsigned int)acc.y);
    float a3 = __uint_as_float((unsigned int)(acc.y >> 32));

    float di = g_dinv[v];
    const float4 bj = __ldg(&((const float4*)b2)[j]);
    float h0 = gelu_t(fmaf(a0, di, bj.x));
    float h1 = gelu_t(fmaf(a1, di, bj.y));
    float h2 = gelu_t(fmaf(a2, di, bj.z));
    float h3 = gelu_t(fmaf(a3, di, bj.w));

    int g = __ldg(&batch[v]);
    red_add_v4(&g_gsum[g * NF + j * 4], h0, h1, h2, h3);
    if (j == 0) atomicAdd(&g_gcnt[g], 1.0f);
}

// K7: final MLP over 256 graphs
__global__ void __launch_bounds__(256) k7_mlp(const float* __restrict__ fc1W,
                                              const float* __restrict__ fc1b,
                                              const float* __restrict__ fc2W,
                                              const float* __restrict__ fc2b,
                                              float* __restrict__ out) {
    __shared__ float W1s[64 * 32];
    __shared__ float b1s[32];
    __shared__ float W2s[32];
    int g = threadIdx.x;
    #pragma unroll
    for (int i = 0; i < 8; i++) W1s[g + i * 256] = fc1W[g + i * 256];
    if (g < 32) { b1s[g] = fc1b[g]; W2s[g] = fc2W[g]; }
    __syncthreads();

    float cnt = g_gcnt[g];
    float inv = 1.0f / fmaxf(cnt, 1.0f);
    float m[64];
    #pragma unroll
    for (int k = 0; k < 64; k++) m[k] = g_gsum[g * 64 + k] * inv;

    float o = 0.0f;
    #pragma unroll 4
    for (int j = 0; j < 32; j++) {
        float z = b1s[j];
        #pragma unroll 8
        for (int k = 0; k < 64; k++) z = fmaf(m[k], W1s[k * 32 + j], z);
        o = fmaf(gelu_t(z), W2s[j], o);
    }
    out[g] = o + fc2b[0];
}

extern "C" void kernel_launch(void* const* d_in, const int* in_sizes, int n_in,
                              void* d_out, int out_size) {
    const float* x     = (const float*)d_in[0];
    const int*   ei    = (const int*)d_in[1];     // int32 (JAX x64 disabled)
    const float* ew    = (const float*)d_in[2];
    const int*   batch = (const int*)d_in[3];
    const float* W1    = (const float*)d_in[4];
    const float* b1    = (const float*)d_in[5];
    const float* W2    = (const float*)d_in[6];
    const float* b2    = (const float*)d_in[7];
    const float* fc1W  = (const float*)d_in[8];
    const float* fc1b  = (const float*)d_in[9];
    const float* fc2W  = (const float*)d_in[10];
    const float* fc2b  = (const float*)d_in[11];
    float* out = (float*)d_out;

    k0_init<<<(NN + 255) / 256, 256>>>();
    k1_hist<<<(NE / 4 + 255) / 256, 256>>>(ei);
    k_scan<<<NBLK, 1024>>>();
    k_place<<<(NE / 4 + 255) / 256, 256>>>(ei, ew);   // launch idx 3 -> profiled
    kA_degnorm<<<(NN + 255) / 256, 256>>>(x);
    k3b_gatherA<<<(NN + 255) / 256, 256>>>();
    k4_layer1<<<NN / 4, dim3(64, 4)>>>(W1, b1, W2);
    k5b_gatherB<<<(NN * 16 + 255) / 256, 256>>>(batch, b2);
    k7_mlp<<<1, 256>>>(fc1W, fc1b, fc2W, fc2b, out);
}

// round 14
// speedup vs baseline: 1.4866x; 1.0085x over previous
#include <cuda_runtime.h>
#include <cuda_bf16.h>
#include <cstdint>

#define NN 100000
#define NE 3200000
#define NG 256
#define NF 64
#define NBLK 98   // ceil(NN/1024)

// -------- scratch (no allocations allowed) --------
__device__ float  g_dinv[NN];
__device__ float  g_p[NN];                  // x * dinv
__device__ float  g_a[NN];                  // layer-1 aggregate
__device__ int    g_icnt[NN];               // in-degree histogram
__device__ int    g_off[NN];                // CSR offsets (exclusive scan)
__device__ int    g_rank[NE];               // rank of edge within its dst row
__device__ int    g_bflag[NBLK];            // scan lookback flags (agg+1, 0=not ready)
__device__ unsigned long long g_epack[NE];  // dst-sorted edges: (w<<32)|r
__device__ float4 g_s[NN * 16];             // s1 = (h1 @ W2) * dinv  [N,64] fp32
__device__ float  g_gsum[NG * NF];
__device__ float  g_gcnt[NG];

__device__ __forceinline__ float gelu_t(float x) {
    const float c = 0.7978845608028654f;
    float t = tanhf(c * (x + 0.044715f * x * x * x));
    return 0.5f * x * (1.0f + t);
}

__device__ __forceinline__ void red_add_v2(float* addr, float a, float b) {
    asm volatile("red.global.add.v2.f32 [%0], {%1,%2};"
                 :: "l"(addr), "f"(a), "f"(b) : "memory");
}

// packed dual-FMA: d = a*b + c elementwise on f32x2 (bit-identical to 2x fmaf)
__device__ __forceinline__ unsigned long long fma2(unsigned long long a,
                                                   unsigned long long b,
                                                   unsigned long long c) {
    unsigned long long d;
    asm("fma.rn.f32x2 %0, %1, %2, %3;" : "=l"(d) : "l"(a), "l"(b), "l"(c));
    return d;
}

// K0: zero histogram + scan flags (every graph replay)
__global__ void k0_init() {
    int i = blockIdx.x * blockDim.x + threadIdx.x;
    if (i < NN) g_icnt[i] = 0;
    if (i < NBLK) g_bflag[i] = 0;
}

// K1: histogram (4 edges/thread); atomic return = rank in dst row
__global__ void __launch_bounds__(256) k1_hist(const int* __restrict__ ei) {
    int e4 = (blockIdx.x * blockDim.x + threadIdx.x) * 4;
    if (e4 >= NE) return;
    int4 cc = __ldg((const int4*)&ei[NE + e4]);
    int4 rk;
    rk.x = atomicAdd(&g_icnt[cc.x], 1);
    rk.y = atomicAdd(&g_icnt[cc.y], 1);
    rk.z = atomicAdd(&g_icnt[cc.z], 1);
    rk.w = atomicAdd(&g_icnt[cc.w], 1);
    *(int4*)&g_rank[e4] = rk;
}

// K_SCAN: single-kernel exclusive scan via decoupled lookback (all 98 blocks co-resident).
__global__ void __launch_bounds__(1024) k_scan() {
    __shared__ int wsum[32];
    __shared__ int s_prefix;
    int t = threadIdx.x, b = blockIdx.x;
    int i = b * 1024 + t;
    int v = (i < NN) ? g_icnt[i] : 0;
    int lane = t & 31, wid = t >> 5;
    int s = v;
    #pragma unroll
    for (int d = 1; d < 32; d <<= 1) {
        int u = __shfl_up_sync(0xffffffffu, s, d);
        if (lane >= d) s += u;
    }
    if (lane == 31) wsum[wid] = s;
    __syncthreads();
    if (wid == 0) {
        int ws = wsum[lane];
        #pragma unroll
        for (int d = 1; d < 32; d <<= 1) {
            int u = __shfl_up_sync(0xffffffffu, ws, d);
            if (lane >= d) ws += u;
        }
        wsum[lane] = ws;
    }
    __syncthreads();
    int excl = s - v + (wid > 0 ? wsum[wid - 1] : 0);

    if (t == 0) atomicExch(&g_bflag[b], wsum[31] + 1);
    if (t < 32) {
        int acc = 0;
        for (int idx = t; idx < b; idx += 32) {
            int f;
            do { f = ((volatile int*)g_bflag)[idx]; } while (f == 0);
            acc += f - 1;
        }
        #pragma unroll
        for (int d = 16; d >= 1; d >>= 1)
            acc += __shfl_xor_sync(0xffffffffu, acc, d);
        if (t == 0) s_prefix = acc;
    }
    __syncthreads();
    if (i < NN) g_off[i] = excl + s_prefix;
}

// KP: placement scatter (no atomics), 4 edges/thread
__global__ void __launch_bounds__(256) k_place(const int* __restrict__ ei,
                                               const float* __restrict__ ew) {
    int e4 = (blockIdx.x * blockDim.x + threadIdx.x) * 4;
    if (e4 >= NE) return;
    int4   rr = __ldg((const int4*)&ei[e4]);
    int4   cc = __ldg((const int4*)&ei[NE + e4]);
    float4 ww = __ldg((const float4*)&ew[e4]);
    int4   rk = *(const int4*)&g_rank[e4];
    g_epack[g_off[cc.x] + rk.x] = ((unsigned long long)__float_as_uint(ww.x) << 32) | (unsigned int)rr.x;
    g_epack[g_off[cc.y] + rk.y] = ((unsigned long long)__float_as_uint(ww.y) << 32) | (unsigned int)rr.y;
    g_epack[g_off[cc.z] + rk.z] = ((unsigned long long)__float_as_uint(ww.z) << 32) | (unsigned int)rr.z;
    g_epack[g_off[cc.w] + rk.w] = ((unsigned long long)__float_as_uint(ww.w) << 32) | (unsigned int)rr.w;
}

// KA: per-node weighted degree from CSR row (+self loop), dinv, p = x*dinv
__global__ void __launch_bounds__(256) kA_degnorm(const float* __restrict__ x) {
    int v = blockIdx.x * blockDim.x + threadIdx.x;
    if (v >= NN) return;
    float deg = 1.0f;
    int i = g_off[v];
    int end = i + g_icnt[v];
    #pragma unroll 4
    for (; i < end; i++) {
        unsigned long long pk = __ldg(&g_epack[i]);
        deg += __uint_as_float((unsigned int)(pk >> 32));
    }
    float d = rsqrtf(deg);
    g_dinv[v] = d;
    g_p[v] = x[v] * d;
}

// K3b: layer-1 aggregation, gather form: a[v] = p[v] + sum p[r]*w
__global__ void __launch_bounds__(256) k3b_gatherA() {
    int v = blockIdx.x * blockDim.x + threadIdx.x;
    if (v >= NN) return;
    float acc = g_p[v];
    int i = g_off[v];
    int end = i + g_icnt[v];
    #pragma unroll 4
    for (; i < end; i++) {
        unsigned long long pk = __ldg(&g_epack[i]);
        int   r = (int)(pk & 0xffffffffu);
        float w = __uint_as_float((unsigned int)(pk >> 32));
        acc = fmaf(w, g_p[r], acc);
    }
    g_a[v] = acc;
}

// K4: h1 = gelu(a*dinv*W1 + b1); s1 = (h1 @ W2)*dinv  (fp32)
// 32 nodes per block: W2 smem load amortized 8x vs 4-node blocks.
// Also zeroes the pool buffers (consumed by k5b which runs later).
__global__ void __launch_bounds__(256) k4_layer1(const float* __restrict__ W1,
                                                 const float* __restrict__ b1,
                                                 const float* __restrict__ W2) {
    __shared__ float W2s[NF * NF];
    __shared__ float hbuf[4][NF];
    int f  = threadIdx.x;
    int ny = threadIdx.y;
    int tid = ny * 64 + f;
    int gid = blockIdx.x * 256 + tid;
    if (gid < NG * NF) g_gsum[gid] = 0.0f;
    if (gid < NG) g_gcnt[gid] = 0.0f;
    #pragma unroll
    for (int i = 0; i < 16; i++) W2s[tid + i * 256] = W2[tid + i * 256];

    float w1f = __ldg(&W1[f]);
    float b1f = __ldg(&b1[f]);

    #pragma unroll 1
    for (int grp = 0; grp < 8; grp++) {
        int v = blockIdx.x * 32 + grp * 4 + ny;   // NN % 32 == 0
        float ad = g_a[v] * g_dinv[v];
        float h = gelu_t(ad * w1f + b1f);
        __syncthreads();
        hbuf[ny][f] = h;
        __syncthreads();
        float t = 0.0f;
        #pragma unroll 8
        for (int k = 0; k < NF; k++) t = fmaf(hbuf[ny][k], W2s[k * NF + f], t);
        ((float*)g_s)[v * NF + f] = t * g_dinv[v];
    }
}

// K5b: layer-2 gather fused with gelu + pool. WARP = NODE.
// Lane j owns float2 slice [2j, 2j+1]. 32-edge chunks loaded cooperatively
// (one edge per lane), broadcast via full-warp shfl; pads carry r=-1 and are
// skipped by a warp-UNIFORM branch (no junk loads).
__global__ void __launch_bounds__(256) k5b_gatherB(const int* __restrict__ batch,
                                                   const float* __restrict__ b2) {
    int v = (blockIdx.x * blockDim.x + threadIdx.x) >> 5;   // node = warp
    int lane = threadIdx.x & 31;
    if (v >= NN) return;

    const unsigned long long* s2 = (const unsigned long long*)g_s;  // float2 rows
    unsigned long long acc = s2[v * 32 + lane];   // self-loop term
    int i = g_off[v];
    int end = i + g_icnt[v];

    for (; i < end; i += 32) {
        int idx = i + lane;
        unsigned long long pk = (idx < end) ? __ldg(&g_epack[idx])
                                            : 0x00000000FFFFFFFFULL;  // r=-1 pad
        #pragma unroll 4
        for (int k = 0; k < 32; k++) {
            unsigned long long pkk = __shfl_sync(0xffffffffu, pk, k);
            int r = (int)(pkk & 0xffffffffu);
            if (r >= 0) {                              // warp-uniform
                unsigned int wu = (unsigned int)(pkk >> 32);
                unsigned long long ww;
                asm("mov.b64 %0, {%1, %1};" : "=l"(ww) : "r"(wu));
                unsigned long long sv = __ldg(&s2[r * 32 + lane]);
                acc = fma2(sv, ww, acc);
            }
        }
    }

    float a0 = __uint_as_float((unsigned int)acc);
    float a1 = __uint_as_float((unsigned int)(acc >> 32));
    float di = g_dinv[v];
    const float2 bj = __ldg(&((const float2*)b2)[lane]);
    float h0 = gelu_t(fmaf(a0, di, bj.x));
    float h1 = gelu_t(fmaf(a1, di, bj.y));

    int g = __ldg(&batch[v]);
    red_add_v2(&g_gsum[g * NF + lane * 2], h0, h1);
    if (lane == 0) atomicAdd(&g_gcnt[g], 1.0f);
}

// K7: final MLP over 256 graphs
__global__ void __launch_bounds__(256) k7_mlp(const float* __restrict__ fc1W,
                                              const float* __restrict__ fc1b,
                                              const float* __restrict__ fc2W,
                                              const float* __restrict__ fc2b,
                                              float* __restrict__ out) {
    __shared__ float W1s[64 * 32];
    __shared__ float b1s[32];
    __shared__ float W2s[32];
    int g = threadIdx.x;
    #pragma unroll
    for (int i = 0; i < 8; i++) W1s[g + i * 256] = fc1W[g + i * 256];
    if (g < 32) { b1s[g] = fc1b[g]; W2s[g] = fc2W[g]; }
    __syncthreads();

    float cnt = g_gcnt[g];
    float inv = 1.0f / fmaxf(cnt, 1.0f);
    float m[64];
    #pragma unroll
    for (int k = 0; k < 64; k++) m[k] = g_gsum[g * 64 + k] * inv;

    float o = 0.0f;
    #pragma unroll 4
    for (int j = 0; j < 32; j++) {
        float z = b1s[j];
        #pragma unroll 8
        for (int k = 0; k < 64; k++) z = fmaf(m[k], W1s[k * 32 + j], z);
        o = fmaf(gelu_t(z), W2s[j], o);
    }
    out[g] = o + fc2b[0];
}

extern "C" void kernel_launch(void* const* d_in, const int* in_sizes, int n_in,
                              void* d_out, int out_size) {
    const float* x     = (const float*)d_in[0];
    const int*   ei    = (const int*)d_in[1];     // int32 (JAX x64 disabled)
    const float* ew    = (const float*)d_in[2];
    const int*   batch = (const int*)d_in[3];
    const float* W1    = (const float*)d_in[4];
    const float* b1    = (const float*)d_in[5];
    const float* W2    = (const float*)d_in[6];
    const float* b2    = (const float*)d_in[7];
    const float* fc1W  = (const float*)d_in[8];
    const float* fc1b  = (const float*)d_in[9];
    const float* fc2W  = (const float*)d_in[10];
    const float* fc2b  = (const float*)d_in[11];
    float* out = (float*)d_out;

    k0_init<<<(NN + 255) / 256, 256>>>();
    k1_hist<<<(NE / 4 + 255) / 256, 256>>>(ei);
    k_scan<<<NBLK, 1024>>>();
    k_place<<<(NE / 4 + 255) / 256, 256>>>(ei, ew);
    kA_degnorm<<<(NN + 255) / 256, 256>>>(x);
    k3b_gatherA<<<(NN + 255) / 256, 256>>>();
    k4_layer1<<<NN / 32, dim3(64, 4)>>>(W1, b1, W2);
    k5b_gatherB<<<(NN * 32 + 255) / 256, 256>>>(batch, b2);
    k7_mlp<<<1, 256>>>(fc1W, fc1b, fc2W, fc2b, out);
}